// round 14
// baseline (speedup 1.0000x reference)
#include <cuda_runtime.h>
#include <cuda_fp16.h>
#include <math.h>
#include <stdint.h>

// Problem constants
#define NB   4
#define CC   128
#define HH   128
#define WW   256
#define HWSZ (HH * WW)          // 32768
#define NHW  (NB * HWSZ)        // 131072
#define DIM  128
#define NWP  4
#define MT   4                  // m-tiles per CTA
#define NCH  (MT * 4)           // 16 chunks per CTA
#define APH  136                // A pitch (half2 units); 136%32==8 -> conflict-free
#define A_STG_H2 (16 * APH)     // half2 per A stage
#define KV_BPR 260              // kv B pitch (uint2); words 520 %32==8
#define Q_BPR  132              // q  B pitch (uint2); words 264 %32==8
#define NBLK_GEMM (NHW / (128 * MT))   // 256
#define NBLK_BIAS 8

// Device-global scratch: K/V/Q fp16 (fp32 accumulate everywhere)
__device__ __half g_K[(size_t)NHW * DIM];
__device__ __half g_V[(size_t)NHW * DIM];
__device__ __half g_Q[(size_t)NHW * DIM];
__device__ float  g_kb[NWP * DIM];
__device__ float  g_vb[NWP * DIM];

__device__ __forceinline__ float inv_dt(int t2) {
    return exp2f(-(float)t2 * (13.287712379549449f / 32.0f));
}
__device__ __forceinline__ uint32_t h2bits(__half2 h) {
    return *reinterpret_cast<uint32_t*>(&h);
}

__device__ __forceinline__ void mma_f16(float d[4], const uint32_t a[4],
                                        uint32_t b0, uint32_t b1) {
    asm volatile(
        "mma.sync.aligned.m16n8k16.row.col.f32.f16.f16.f32 "
        "{%0,%1,%2,%3}, {%4,%5,%6,%7}, {%8,%9}, {%0,%1,%2,%3};\n"
        : "+f"(d[0]), "+f"(d[1]), "+f"(d[2]), "+f"(d[3])
        : "r"(a[0]), "r"(a[1]), "r"(a[2]), "r"(a[3]), "r"(b0), "r"(b1));
}

// Shuffle-transpose 4 col-pair half2s across the 4 q-lanes so each lane gets
// 16 contiguous bytes (cols q*8 .. q*8+7). val[nj] = cols nj*8 + 2q (+1).
__device__ __forceinline__ uint4 gather16B(const uint32_t val[4], int lane, int q) {
    uint32_t u[4];
#pragma unroll
    for (int k = 0; k < 4; ++k) {
        int jsrc = (q + k) & 3;
        uint32_t send = val[(q - k) & 3];
        uint32_t r = __shfl_sync(0xffffffffu, send, (lane & ~3) | jsrc);
        u[jsrc] = r;
    }
    return make_uint4(u[0], u[1], u[2], u[3]);
}

// ---------------------------------------------------------------------------
// Bias path (blocks 0..7); threads 0..511 active
// ---------------------------------------------------------------------------
__device__ void bias_path(int bid, int t,
                          const float* __restrict__ kw, const float* __restrict__ kb,
                          const float* __restrict__ vw, const float* __restrict__ vb) {
    __shared__ float pb[DIM];
    int w      = bid & 3;
    int matrix = bid >> 2;
    if (t < DIM) {
        int oy = w >> 1, ox = w & 1;
        float coord = (t < 64) ? (float)oy : (float)ox;
        int ii = t & 63;
        int t2 = ii >> 1;
        float arg = coord * (6.283185307179586f / 1.000001f) * inv_dt(t2);
        float s, c;
        sincosf(arg, &s, &c);
        pb[t] = (ii & 1) ? c : s;
    }
    __syncthreads();
    if (t >= 512) return;

    const float* W  = matrix ? vw : kw;
    const float* Bb = matrix ? vb : kb;
    float* dst      = matrix ? g_vb : g_kb;

    int d = t >> 2, q = t & 3;
    float acc = 0.f;
    int cbase = q * 32;
#pragma unroll 8
    for (int c = 0; c < 32; ++c)
        acc += pb[cbase + c] * W[(cbase + c) * DIM + d];
    acc += __shfl_xor_sync(0xffffffffu, acc, 1);
    acc += __shfl_xor_sync(0xffffffffu, acc, 2);
    if (q == 0)
        dst[w * DIM + d] = acc + Bb[d];
}

// ---------------------------------------------------------------------------
// A fill: LDG fp32 -> cvt -> STS fp16 (k-pair layout). 4 smem stages.
// ---------------------------------------------------------------------------
struct ARegs { float2 r0, r1; };

__device__ __forceinline__ void ldgA(ARegs& ra, const float* __restrict__ feat,
                                     int n, int pix0_blk, int gc, int t) {
    int kp = t >> 6, m2 = t & 63;
    int kb = (gc & 3) * 32, tile = gc >> 2;
    int pix = pix0_blk + tile * 128 + m2 * 2;
    const float* p = feat + (size_t)(n * CC + kb + 2 * kp) * HWSZ + pix;
    ra.r0 = *(const float2*)p;
    ra.r1 = *(const float2*)(p + HWSZ);
}

__device__ __forceinline__ void stsA_kv(__half2* __restrict__ Asm,
                                        const ARegs& ra, int gc, int t) {
    int kp = t >> 6, m2 = t & 63;
    __half2* dst = Asm + (gc & 3) * A_STG_H2 + kp * APH + m2 * 2;
    uint2 u;
    u.x = h2bits(__floats2half2_rn(ra.r0.x, ra.r1.x));
    u.y = h2bits(__floats2half2_rn(ra.r0.y, ra.r1.y));
    *(uint2*)dst = u;
}

__device__ __forceinline__ void stsA_q(__half2* __restrict__ Asm, const ARegs& ra,
                                       int gc, int t,
                                       const float* __restrict__ s_base,
                                       const float* __restrict__ s_idt) {
    int kp = t >> 6, m2 = t & 63;
    int kb = (gc & 3) * 32, tile = gc >> 2;
    int c0 = kb + 2 * kp;
    int half = (c0 >> 6) & 1;
    int t2 = (c0 & 63) >> 1;
    float f = s_idt[t2];
    const float* bp = s_base + (half * MT + tile) * 128 + m2 * 2;
    float sa, ca, sb, cb;
    __sincosf(bp[0] * f, &sa, &ca);
    __sincosf(bp[1] * f, &sb, &cb);
    __half2* dst = Asm + (gc & 3) * A_STG_H2 + kp * APH + m2 * 2;
    uint2 u;
    u.x = h2bits(__floats2half2_rn(ra.r0.x + sa, ra.r1.x + ca));
    u.y = h2bits(__floats2half2_rn(ra.r0.y + sb, ra.r1.y + cb));
    *(uint2*)dst = u;
}

// ---------------------------------------------------------------------------
// KV path: 32 warps (4m x 8n), m32 x n32 warp tile; B resident; barrier/2 chunks
// ---------------------------------------------------------------------------
__device__ __forceinline__ void mma_chunk_kv(const __half2* __restrict__ Asm,
                                             const uint2* __restrict__ Bu,
                                             float acc[2][4][4],
                                             int m0w, int n0w, int q, int g) {
#pragma unroll
    for (int kg = 0; kg < 2; ++kg) {
        uint32_t a[2][4];
#pragma unroll
        for (int mi = 0; mi < 2; ++mi) {
            int m = m0w + mi * 16 + g;
            a[mi][0] = *(const uint32_t*)(Asm + (kg * 8 + q) * APH + m);
            a[mi][1] = *(const uint32_t*)(Asm + (kg * 8 + q) * APH + m + 8);
            a[mi][2] = *(const uint32_t*)(Asm + (kg * 8 + q + 4) * APH + m);
            a[mi][3] = *(const uint32_t*)(Asm + (kg * 8 + q + 4) * APH + m + 8);
        }
#pragma unroll
        for (int nj = 0; nj < 4; ++nj) {
            uint2 b = Bu[(kg * 4 + q) * KV_BPR + n0w + nj * 8 + g];
#pragma unroll
            for (int mi = 0; mi < 2; ++mi)
                mma_f16(acc[mi][nj], a[mi], b.x, b.y);
        }
    }
}

__device__ void kv_path(int bid, int t, char* smraw,
                        const float* __restrict__ feat,
                        const float* __restrict__ kw,
                        const float* __restrict__ vw) {
    __half2* Asm = (__half2*)smraw;
    uint2*   Bu  = (uint2*)(smraw + 4 * A_STG_H2 * 4);

    int m0_blk = bid * (128 * MT);
    int n      = m0_blk / HWSZ;
    int pix0_blk = m0_blk % HWSZ;

    ARegs ra[2];
    ldgA(ra[0], feat, n, pix0_blk, 0, t);
    ldgA(ra[1], feat, n, pix0_blk, 1, t);

#pragma unroll
    for (int j = 0; j < 8; ++j) {
        int idx = j * 1024 + t;
        int pr = idx >> 8, nn = idx & 255;
        int cc = pr >> 3, kg = (pr >> 2) & 1, qq = pr & 3;
        int kpp = cc * 16 + kg * 8 + qq;
        const float* W = (nn < 128) ? kw : vw;
        int col = nn & 127;
        float w0 = W[(2 * kpp) * DIM + col];
        float w1 = W[(2 * kpp + 1) * DIM + col];
        float w2 = W[(2 * kpp + 8) * DIM + col];
        float w3 = W[(2 * kpp + 9) * DIM + col];
        uint2 u;
        u.x = h2bits(__floats2half2_rn(w0, w1));
        u.y = h2bits(__floats2half2_rn(w2, w3));
        Bu[pr * KV_BPR + nn] = u;
    }

    stsA_kv(Asm, ra[0], 0, t);
    stsA_kv(Asm, ra[1], 1, t);
    ldgA(ra[0], feat, n, pix0_blk, 2, t);
    ldgA(ra[1], feat, n, pix0_blk, 3, t);
    __syncthreads();

    int w = t >> 5, lane = t & 31;
    int m0w = (w & 3) * 32, n0w = (w >> 2) * 32;
    int q = lane & 3, g = lane >> 2;

    float acc[2][4][4];
#pragma unroll
    for (int mi = 0; mi < 2; ++mi)
#pragma unroll
        for (int nj = 0; nj < 4; ++nj)
#pragma unroll
            for (int e = 0; e < 4; ++e) acc[mi][nj][e] = 0.f;

#pragma unroll 1
    for (int gp = 0; gp < 8; ++gp) {
        int c0 = 2 * gp, c1 = c0 + 1;
        if (gp <= 6) { stsA_kv(Asm, ra[0], c0 + 2, t); stsA_kv(Asm, ra[1], c1 + 2, t); }
        if (gp <= 5) {
            ldgA(ra[0], feat, n, pix0_blk, c0 + 4, t);
            ldgA(ra[1], feat, n, pix0_blk, c1 + 4, t);
        }
        mma_chunk_kv(Asm + (c0 & 3) * A_STG_H2, Bu + ((c0 & 3) * 8) * KV_BPR,
                     acc, m0w, n0w, q, g);
        mma_chunk_kv(Asm + (c1 & 3) * A_STG_H2, Bu + ((c1 & 3) * 8) * KV_BPR,
                     acc, m0w, n0w, q, g);

        if (gp & 1) {
            int m0 = m0_blk + (gp >> 1) * 128;
            int colb = n0w + q * 8;
#pragma unroll
            for (int mi = 0; mi < 2; ++mi) {
#pragma unroll
                for (int half = 0; half < 2; ++half) {
                    uint32_t val[4];
#pragma unroll
                    for (int nj = 0; nj < 4; ++nj)
                        val[nj] = h2bits(__floats2half2_rn(acc[mi][nj][2 * half],
                                                           acc[mi][nj][2 * half + 1]));
                    uint4 u = gather16B(val, lane, q);
                    int row = m0 + m0w + mi * 16 + half * 8 + g;
                    __half* dst = (colb < 128)
                        ? (g_K + (size_t)row * DIM + colb)
                        : (g_V + (size_t)row * DIM + (colb - 128));
                    *(uint4*)dst = u;
                }
#pragma unroll
                for (int nj = 0; nj < 4; ++nj)
#pragma unroll
                    for (int e = 0; e < 4; ++e) acc[mi][nj][e] = 0.f;
            }
        }
        __syncthreads();
    }
}

// ---------------------------------------------------------------------------
// Q path: 32 warps (8m x 4n), m16 x n32 tile; PE fused in fill
// ---------------------------------------------------------------------------
__device__ __forceinline__ void mma_chunk_q(const __half2* __restrict__ Asm,
                                            const uint2* __restrict__ Bu,
                                            float acc[4][4],
                                            int m0w, int n0w, int q, int g) {
#pragma unroll
    for (int kg = 0; kg < 2; ++kg) {
        uint32_t a[4];
        int m = m0w + g;
        a[0] = *(const uint32_t*)(Asm + (kg * 8 + q) * APH + m);
        a[1] = *(const uint32_t*)(Asm + (kg * 8 + q) * APH + m + 8);
        a[2] = *(const uint32_t*)(Asm + (kg * 8 + q + 4) * APH + m);
        a[3] = *(const uint32_t*)(Asm + (kg * 8 + q + 4) * APH + m + 8);
#pragma unroll
        for (int nj = 0; nj < 4; ++nj) {
            uint2 b = Bu[(kg * 4 + q) * Q_BPR + n0w + nj * 8 + g];
            mma_f16(acc[nj], a, b.x, b.y);
        }
    }
}

__device__ void q_path(int bid, int t, char* smraw,
                       const float* __restrict__ feat,
                       const float* __restrict__ flow,
                       const float* __restrict__ qw,
                       const float* __restrict__ qb) {
    __half2* Asm = (__half2*)smraw;
    uint2*   Bu  = (uint2*)(smraw + 4 * A_STG_H2 * 4);
    __shared__ float s_base[2 * MT * 128];
    __shared__ float s_idt[32];

    int m0_blk = bid * (128 * MT);
    int n      = m0_blk / HWSZ;
    int pix0_blk = m0_blk % HWSZ;

    ARegs ra[2];
    ldgA(ra[0], feat, n, pix0_blk, 0, t);
    ldgA(ra[1], feat, n, pix0_blk, 1, t);

#pragma unroll
    for (int j = 0; j < 4; ++j) {
        int idx = j * 1024 + t;
        int pr = idx >> 7, nn = idx & 127;
        int cc = pr >> 3, kg = (pr >> 2) & 1, qq = pr & 3;
        int kpp = cc * 16 + kg * 8 + qq;
        float w0 = qw[(2 * kpp) * DIM + nn];
        float w1 = qw[(2 * kpp + 1) * DIM + nn];
        float w2 = qw[(2 * kpp + 8) * DIM + nn];
        float w3 = qw[(2 * kpp + 9) * DIM + nn];
        uint2 u;
        u.x = h2bits(__floats2half2_rn(w0, w1));
        u.y = h2bits(__floats2half2_rn(w2, w3));
        Bu[pr * Q_BPR + nn] = u;
    }

    if (t < 32) s_idt[t] = inv_dt(t);
    {
        int idx = t;
        int half = idx >> 9;
        int tile = (idx >> 7) & 3;
        int m    = idx & 127;
        int pix  = pix0_blk + tile * 128 + m;
        int yy = pix / WW, xx = pix % WW;
        const float* fl = flow + (size_t)((n * HH + yy) * WW + xx) * 2;
        float fx = fl[0], fy = fl[1];
        float full = half ? ((float)xx + fx) : ((float)yy + fy);
        float dec  = full - floorf(full);
        s_base[(half * MT + tile) * 128 + m] = dec * (6.283185307179586f / 2.000001f);
    }
    __syncthreads();

    stsA_q(Asm, ra[0], 0, t, s_base, s_idt);
    stsA_q(Asm, ra[1], 1, t, s_base, s_idt);
    ldgA(ra[0], feat, n, pix0_blk, 2, t);
    ldgA(ra[1], feat, n, pix0_blk, 3, t);
    __syncthreads();

    int w = t >> 5, lane = t & 31;
    int m0w = (w & 7) * 16, n0w = (w >> 3) * 32;
    int q = lane & 3, g = lane >> 2;

    float acc[4][4];
#pragma unroll
    for (int nj = 0; nj < 4; ++nj)
#pragma unroll
        for (int e = 0; e < 4; ++e) acc[nj][e] = 0.f;

    const float sc = 0.25f;

#pragma unroll 1
    for (int gp = 0; gp < 8; ++gp) {
        int c0 = 2 * gp, c1 = c0 + 1;
        if (gp <= 6) {
            stsA_q(Asm, ra[0], c0 + 2, t, s_base, s_idt);
            stsA_q(Asm, ra[1], c1 + 2, t, s_base, s_idt);
        }
        if (gp <= 5) {
            ldgA(ra[0], feat, n, pix0_blk, c0 + 4, t);
            ldgA(ra[1], feat, n, pix0_blk, c1 + 4, t);
        }
        mma_chunk_q(Asm + (c0 & 3) * A_STG_H2, Bu + ((c0 & 3) * 8) * Q_BPR,
                    acc, m0w, n0w, q, g);
        mma_chunk_q(Asm + (c1 & 3) * A_STG_H2, Bu + ((c1 & 3) * 8) * Q_BPR,
                    acc, m0w, n0w, q, g);

        if (gp & 1) {
            int m0 = m0_blk + (gp >> 1) * 128;
            int colb = n0w + q * 8;
#pragma unroll
            for (int half = 0; half < 2; ++half) {
                uint32_t val[4];
#pragma unroll
                for (int nj = 0; nj < 4; ++nj) {
                    int cb = n0w + nj * 8 + q * 2;
                    float b0 = qb[cb], b1 = qb[cb + 1];
                    val[nj] = h2bits(__floats2half2_rn(
                        (acc[nj][2 * half] + b0) * sc,
                        (acc[nj][2 * half + 1] + b1) * sc));
                }
                uint4 u = gather16B(val, lane, q);
                int row = m0 + m0w + half * 8 + g;
                *(uint4*)(g_Q + (size_t)row * DIM + colb) = u;
            }
#pragma unroll
            for (int nj = 0; nj < 4; ++nj)
#pragma unroll
                for (int e = 0; e < 4; ++e) acc[nj][e] = 0.f;
        }
        __syncthreads();
    }
}

// ---------------------------------------------------------------------------
// Merged prep kernel: [bias | kv | q] by block range (one launch, one tail)
// ---------------------------------------------------------------------------
__global__ __launch_bounds__(1024, 1)
void prep_kernel(const float* __restrict__ feat_supp,
                 const float* __restrict__ feat_curr,
                 const float* __restrict__ flow,
                 const float* __restrict__ qw, const float* __restrict__ qb,
                 const float* __restrict__ kw, const float* __restrict__ kb,
                 const float* __restrict__ vw, const float* __restrict__ vb) {
    extern __shared__ char smraw[];
    int t = threadIdx.x;
    int b = blockIdx.x;
    if (b < NBLK_BIAS) {
        bias_path(b, t, kw, kb, vw, vb);
    } else if (b < NBLK_BIAS + NBLK_GEMM) {
        kv_path(b - NBLK_BIAS, t, smraw, feat_supp, kw, vw);
    } else {
        q_path(b - NBLK_BIAS - NBLK_GEMM, t, smraw, feat_curr, flow, qw, qb);
    }
}

// ---------------------------------------------------------------------------
// Attention (R13 proven): 512 thr, 32 px/CTA, 2 px/warp; head = 2 lanes (xor-1)
// ---------------------------------------------------------------------------
#define OPIT 129

__global__ __launch_bounds__(512, 2)
void attn_kernel(const float* __restrict__ flow, float* __restrict__ out) {
    __shared__ float s_out[32 * OPIT];
    __shared__ float s_kb[NWP * DIM];
    __shared__ float s_vb[NWP * DIM];
    int t = threadIdx.x;
    if (t < NWP * DIM) {
        s_kb[t] = g_kb[t];
        s_vb[t] = g_vb[t];
    }
    __syncthreads();

    int warp = t >> 5, lane = t & 31;
    int sub = lane >> 4, sl = lane & 15;
    int pidx = warp * 2 + sub;
    int p   = blockIdx.x * 32 + pidx;
    int n   = p / HWSZ;
    int pix = p % HWSZ;
    int y = pix / WW, x = pix % WW;

    const float* fl = flow + (size_t)((n * HH + y) * WW + x) * 2;
    float fx = fl[0], fy = fl[1];
    int giy = (int)floorf((float)y + fy);
    int gix = (int)floorf((float)x + fx);

    int c0 = sl * 8;
    uint4 qraw = *(const uint4*)(g_Q + (size_t)p * DIM + c0);
    float2 q01 = __half22float2(*(__half2*)&qraw.x);
    float2 q23 = __half22float2(*(__half2*)&qraw.y);
    float2 q45 = __half22float2(*(__half2*)&qraw.z);
    float2 q67 = __half22float2(*(__half2*)&qraw.w);

    int nb[4];
#pragma unroll
    for (int w2 = 0; w2 < 4; ++w2) {
        int hy = giy + (w2 >> 1);
        int wx = gix + (w2 & 1);
        hy = hy < 0 ? 0 : (hy > HH - 1 ? HH - 1 : hy);
        wx = wx < 0 ? 0 : (wx > WW - 1 ? WW - 1 : wx);
        nb[w2] = n * HWSZ + hy * WW + wx;
    }
    uint4 kraw[4], vraw[4];
#pragma unroll
    for (int w2 = 0; w2 < 4; ++w2) {
        kraw[w2] = *(const uint4*)(g_K + (size_t)nb[w2] * DIM + c0);
        vraw[w2] = *(const uint4*)(g_V + (size_t)nb[w2] * DIM + c0);
    }

    float lg[4];
#pragma unroll
    for (int w2 = 0; w2 < 4; ++w2) {
        float2 k01 = __half22float2(*(__half2*)&kraw[w2].x);
        float2 k23 = __half22float2(*(__half2*)&kraw[w2].y);
        float2 k45 = __half22float2(*(__half2*)&kraw[w2].z);
        float2 k67 = __half22float2(*(__half2*)&kraw[w2].w);
        const float* kbp = s_kb + w2 * DIM + c0;
        float part = q01.x * (k01.x + kbp[0]) + q01.y * (k01.y + kbp[1]) +
                     q23.x * (k23.x + kbp[2]) + q23.y * (k23.y + kbp[3]) +
                     q45.x * (k45.x + kbp[4]) + q45.y * (k45.y + kbp[5]) +
                     q67.x * (k67.x + kbp[6]) + q67.y * (k67.y + kbp[7]);
        part += __shfl_xor_sync(0xffffffffu, part, 1);   // head = 2 lanes
        lg[w2] = part;
    }
    float mx = fmaxf(fmaxf(lg[0], lg[1]), fmaxf(lg[2], lg[3]));
    float e0 = __expf(lg[0] - mx), e1 = __expf(lg[1] - mx);
    float e2 = __expf(lg[2] - mx), e3 = __expf(lg[3] - mx);
    float inv = 1.f / (e0 + e1 + e2 + e3);
    float aw[4] = {e0 * inv, e1 * inv, e2 * inv, e3 * inv};

    float o[8] = {0.f, 0.f, 0.f, 0.f, 0.f, 0.f, 0.f, 0.f};
#pragma unroll
    for (int w2 = 0; w2 < 4; ++w2) {
        float2 v01 = __half22float2(*(__half2*)&vraw[w2].x);
        float2 v23 = __half22float2(*(__half2*)&vraw[w2].y);
        float2 v45 = __half22float2(*(__half2*)&vraw[w2].z);
        float2 v67 = __half22float2(*(__half2*)&vraw[w2].w);
        const float* vbp = s_vb + w2 * DIM + c0;
        float a = aw[w2];
        o[0] += a * (v01.x + vbp[0]);
        o[1] += a * (v01.y + vbp[1]);
        o[2] += a * (v23.x + vbp[2]);
        o[3] += a * (v23.y + vbp[3]);
        o[4] += a * (v45.x + vbp[4]);
        o[5] += a * (v45.y + vbp[5]);
        o[6] += a * (v67.x + vbp[6]);
        o[7] += a * (v67.y + vbp[7]);
    }
#pragma unroll
    for (int i = 0; i < 8; ++i)
        s_out[pidx * OPIT + c0 + i] = o[i];
    __syncthreads();

    int p0   = blockIdx.x * 32;
    int n0   = p0 / HWSZ;
    int pix0 = p0 % HWSZ;
    int y0 = pix0 / WW, x0 = pix0 % WW;
#pragma unroll
    for (int j = 0; j < 8; ++j) {
        int d = warp + j * 16;
        out[((size_t)(n0 * DIM + d) * HH + y0) * WW + x0 + lane] =
            s_out[lane * OPIT + d];
    }
}

// ---------------------------------------------------------------------------
extern "C" void kernel_launch(void* const* d_in, const int* in_sizes, int n_in,
                              void* d_out, int out_size) {
    const float* feat_supp = (const float*)d_in[0];
    const float* feat_curr = (const float*)d_in[1];
    const float* flow      = (const float*)d_in[2];
    const float* q_w       = (const float*)d_in[3];
    const float* q_b       = (const float*)d_in[4];
    const float* k_w       = (const float*)d_in[5];
    const float* k_b       = (const float*)d_in[6];
    const float* v_w       = (const float*)d_in[7];
    const float* v_b       = (const float*)d_in[8];
    float* out = (float*)d_out;

    const int smem_prep = 4 * A_STG_H2 * 4 + 32 * KV_BPR * 8;  // 101376 B
    cudaFuncSetAttribute(prep_kernel, cudaFuncAttributeMaxDynamicSharedMemorySize, smem_prep);

    prep_kernel<<<NBLK_BIAS + 2 * NBLK_GEMM, 1024, smem_prep>>>(
        feat_supp, feat_curr, flow, q_w, q_b, k_w, k_b, v_w, v_b);
    attn_kernel<<<NHW / 32, 512>>>(flow, out);
}

// round 15
// speedup vs baseline: 1.2489x; 1.2489x over previous
#include <cuda_runtime.h>
#include <cuda_fp16.h>
#include <math.h>
#include <stdint.h>

// Problem constants
#define NB   4
#define CC   128
#define HH   128
#define WW   256
#define HWSZ (HH * WW)          // 32768
#define NHW  (NB * HWSZ)        // 131072
#define DIM  128
#define NWP  4
#define MT   4                  // m-tiles per CTA
#define NCH  (MT * 4)           // 16 chunks per CTA
#define APH  136                // A pitch (half2 units); 136%32==8 -> conflict-free
#define A_STG_H2 (16 * APH)     // half2 per A stage
#define KV_BPR 260              // kv B pitch (uint2); words 520 %32==8
#define Q_BPR  132              // q  B pitch (uint2); words 264 %32==8
#define NBLK_GEMM (NHW / (128 * MT))   // 256
#define NBLK_BIAS 8

// Device-global scratch: K/V/Q fp16 (fp32 accumulate everywhere)
__device__ __half g_K[(size_t)NHW * DIM];
__device__ __half g_V[(size_t)NHW * DIM];
__device__ __half g_Q[(size_t)NHW * DIM];
__device__ float  g_kb[NWP * DIM];
__device__ float  g_vb[NWP * DIM];

__device__ __forceinline__ float inv_dt(int t2) {
    return exp2f(-(float)t2 * (13.287712379549449f / 32.0f));
}
__device__ __forceinline__ uint32_t h2bits(__half2 h) {
    return *reinterpret_cast<uint32_t*>(&h);
}

__device__ __forceinline__ void mma_f16(float d[4], const uint32_t a[4],
                                        uint32_t b0, uint32_t b1) {
    asm volatile(
        "mma.sync.aligned.m16n8k16.row.col.f32.f16.f16.f32 "
        "{%0,%1,%2,%3}, {%4,%5,%6,%7}, {%8,%9}, {%0,%1,%2,%3};\n"
        : "+f"(d[0]), "+f"(d[1]), "+f"(d[2]), "+f"(d[3])
        : "r"(a[0]), "r"(a[1]), "r"(a[2]), "r"(a[3]), "r"(b0), "r"(b1));
}

// ---------------------------------------------------------------------------
// Bias path (blocks 0..7); threads 0..511 active
// ---------------------------------------------------------------------------
__device__ void bias_path(int bid, int t,
                          const float* __restrict__ kw, const float* __restrict__ kb,
                          const float* __restrict__ vw, const float* __restrict__ vb) {
    __shared__ float pb[DIM];
    int w      = bid & 3;
    int matrix = bid >> 2;
    if (t < DIM) {
        int oy = w >> 1, ox = w & 1;
        float coord = (t < 64) ? (float)oy : (float)ox;
        int ii = t & 63;
        int t2 = ii >> 1;
        float arg = coord * (6.283185307179586f / 1.000001f) * inv_dt(t2);
        float s, c;
        sincosf(arg, &s, &c);
        pb[t] = (ii & 1) ? c : s;
    }
    __syncthreads();
    if (t >= 512) return;

    const float* W  = matrix ? vw : kw;
    const float* Bb = matrix ? vb : kb;
    float* dst      = matrix ? g_vb : g_kb;

    int d = t >> 2, q = t & 3;
    float acc = 0.f;
    int cbase = q * 32;
#pragma unroll 8
    for (int c = 0; c < 32; ++c)
        acc += pb[cbase + c] * W[(cbase + c) * DIM + d];
    acc += __shfl_xor_sync(0xffffffffu, acc, 1);
    acc += __shfl_xor_sync(0xffffffffu, acc, 2);
    if (q == 0)
        dst[w * DIM + d] = acc + Bb[d];
}

// ---------------------------------------------------------------------------
// A fill: LDG fp32 -> cvt -> STS fp16 (k-pair layout). 4 smem stages.
// ---------------------------------------------------------------------------
struct ARegs { float2 r0, r1; };

__device__ __forceinline__ void ldgA(ARegs& ra, const float* __restrict__ feat,
                                     int n, int pix0_blk, int gc, int t) {
    int kp = t >> 6, m2 = t & 63;
    int kb = (gc & 3) * 32, tile = gc >> 2;
    int pix = pix0_blk + tile * 128 + m2 * 2;
    const float* p = feat + (size_t)(n * CC + kb + 2 * kp) * HWSZ + pix;
    ra.r0 = *(const float2*)p;
    ra.r1 = *(const float2*)(p + HWSZ);
}

__device__ __forceinline__ void stsA_kv(__half2* __restrict__ Asm,
                                        const ARegs& ra, int gc, int t) {
    int kp = t >> 6, m2 = t & 63;
    __half2* dst = Asm + (gc & 3) * A_STG_H2 + kp * APH + m2 * 2;
    uint2 u;
    u.x = h2bits(__floats2half2_rn(ra.r0.x, ra.r1.x));
    u.y = h2bits(__floats2half2_rn(ra.r0.y, ra.r1.y));
    *(uint2*)dst = u;
}

__device__ __forceinline__ void stsA_q(__half2* __restrict__ Asm, const ARegs& ra,
                                       int gc, int t,
                                       const float* __restrict__ s_base,
                                       const float* __restrict__ s_idt) {
    int kp = t >> 6, m2 = t & 63;
    int kb = (gc & 3) * 32, tile = gc >> 2;
    int c0 = kb + 2 * kp;
    int half = (c0 >> 6) & 1;
    int t2 = (c0 & 63) >> 1;
    float f = s_idt[t2];
    const float* bp = s_base + (half * MT + tile) * 128 + m2 * 2;
    float sa, ca, sb, cb;
    __sincosf(bp[0] * f, &sa, &ca);
    __sincosf(bp[1] * f, &sb, &cb);
    __half2* dst = Asm + (gc & 3) * A_STG_H2 + kp * APH + m2 * 2;
    uint2 u;
    u.x = h2bits(__floats2half2_rn(ra.r0.x + sa, ra.r1.x + ca));
    u.y = h2bits(__floats2half2_rn(ra.r0.y + sb, ra.r1.y + cb));
    *(uint2*)dst = u;
}

// ---------------------------------------------------------------------------
// KV path: 32 warps (4m x 8n), m32 x n32 warp tile; B resident; barrier/2 chunks
// (R13 epilogue — half2 stores; L2 merges adjacent q-lane segments)
// ---------------------------------------------------------------------------
__device__ __forceinline__ void mma_chunk_kv(const __half2* __restrict__ Asm,
                                             const uint2* __restrict__ Bu,
                                             float acc[2][4][4],
                                             int m0w, int n0w, int q, int g) {
#pragma unroll
    for (int kg = 0; kg < 2; ++kg) {
        uint32_t a[2][4];
#pragma unroll
        for (int mi = 0; mi < 2; ++mi) {
            int m = m0w + mi * 16 + g;
            a[mi][0] = *(const uint32_t*)(Asm + (kg * 8 + q) * APH + m);
            a[mi][1] = *(const uint32_t*)(Asm + (kg * 8 + q) * APH + m + 8);
            a[mi][2] = *(const uint32_t*)(Asm + (kg * 8 + q + 4) * APH + m);
            a[mi][3] = *(const uint32_t*)(Asm + (kg * 8 + q + 4) * APH + m + 8);
        }
#pragma unroll
        for (int nj = 0; nj < 4; ++nj) {
            uint2 b = Bu[(kg * 4 + q) * KV_BPR + n0w + nj * 8 + g];
#pragma unroll
            for (int mi = 0; mi < 2; ++mi)
                mma_f16(acc[mi][nj], a[mi], b.x, b.y);
        }
    }
}

__device__ void kv_path(int bid, int t, char* smraw,
                        const float* __restrict__ feat,
                        const float* __restrict__ kw,
                        const float* __restrict__ vw) {
    __half2* Asm = (__half2*)smraw;
    uint2*   Bu  = (uint2*)(smraw + 4 * A_STG_H2 * 4);

    int m0_blk = bid * (128 * MT);
    int n      = m0_blk / HWSZ;
    int pix0_blk = m0_blk % HWSZ;

    ARegs ra[2];
    ldgA(ra[0], feat, n, pix0_blk, 0, t);
    ldgA(ra[1], feat, n, pix0_blk, 1, t);

#pragma unroll
    for (int j = 0; j < 8; ++j) {
        int idx = j * 1024 + t;
        int pr = idx >> 8, nn = idx & 255;
        int cc = pr >> 3, kg = (pr >> 2) & 1, qq = pr & 3;
        int kpp = cc * 16 + kg * 8 + qq;
        const float* W = (nn < 128) ? kw : vw;
        int col = nn & 127;
        float w0 = W[(2 * kpp) * DIM + col];
        float w1 = W[(2 * kpp + 1) * DIM + col];
        float w2 = W[(2 * kpp + 8) * DIM + col];
        float w3 = W[(2 * kpp + 9) * DIM + col];
        uint2 u;
        u.x = h2bits(__floats2half2_rn(w0, w1));
        u.y = h2bits(__floats2half2_rn(w2, w3));
        Bu[pr * KV_BPR + nn] = u;
    }

    stsA_kv(Asm, ra[0], 0, t);
    stsA_kv(Asm, ra[1], 1, t);
    ldgA(ra[0], feat, n, pix0_blk, 2, t);
    ldgA(ra[1], feat, n, pix0_blk, 3, t);
    __syncthreads();

    int w = t >> 5, lane = t & 31;
    int m0w = (w & 3) * 32, n0w = (w >> 2) * 32;
    int q = lane & 3, g = lane >> 2;

    float acc[2][4][4];
#pragma unroll
    for (int mi = 0; mi < 2; ++mi)
#pragma unroll
        for (int nj = 0; nj < 4; ++nj)
#pragma unroll
            for (int e = 0; e < 4; ++e) acc[mi][nj][e] = 0.f;

#pragma unroll 1
    for (int gp = 0; gp < 8; ++gp) {
        int c0 = 2 * gp, c1 = c0 + 1;
        if (gp <= 6) { stsA_kv(Asm, ra[0], c0 + 2, t); stsA_kv(Asm, ra[1], c1 + 2, t); }
        if (gp <= 5) {
            ldgA(ra[0], feat, n, pix0_blk, c0 + 4, t);
            ldgA(ra[1], feat, n, pix0_blk, c1 + 4, t);
        }
        mma_chunk_kv(Asm + (c0 & 3) * A_STG_H2, Bu + ((c0 & 3) * 8) * KV_BPR,
                     acc, m0w, n0w, q, g);
        mma_chunk_kv(Asm + (c1 & 3) * A_STG_H2, Bu + ((c1 & 3) * 8) * KV_BPR,
                     acc, m0w, n0w, q, g);

        if (gp & 1) {
            int m0 = m0_blk + (gp >> 1) * 128;
#pragma unroll
            for (int mi = 0; mi < 2; ++mi) {
#pragma unroll
                for (int nj = 0; nj < 4; ++nj) {
                    int r0 = m0 + m0w + mi * 16 + g;
                    int col = n0w + nj * 8 + q * 2;
                    __half* dst = (col < 128) ? (g_K + (size_t)r0 * DIM + col)
                                              : (g_V + (size_t)r0 * DIM + (col - 128));
                    *(__half2*)dst = __floats2half2_rn(acc[mi][nj][0], acc[mi][nj][1]);
                    *(__half2*)(dst + (size_t)8 * DIM) =
                        __floats2half2_rn(acc[mi][nj][2], acc[mi][nj][3]);
                    acc[mi][nj][0] = 0.f; acc[mi][nj][1] = 0.f;
                    acc[mi][nj][2] = 0.f; acc[mi][nj][3] = 0.f;
                }
            }
        }
        __syncthreads();
    }
}

// ---------------------------------------------------------------------------
// Q path: 32 warps (8m x 4n), m16 x n32 tile; PE fused in fill (R13 epilogue)
// ---------------------------------------------------------------------------
__device__ __forceinline__ void mma_chunk_q(const __half2* __restrict__ Asm,
                                            const uint2* __restrict__ Bu,
                                            float acc[4][4],
                                            int m0w, int n0w, int q, int g) {
#pragma unroll
    for (int kg = 0; kg < 2; ++kg) {
        uint32_t a[4];
        int m = m0w + g;
        a[0] = *(const uint32_t*)(Asm + (kg * 8 + q) * APH + m);
        a[1] = *(const uint32_t*)(Asm + (kg * 8 + q) * APH + m + 8);
        a[2] = *(const uint32_t*)(Asm + (kg * 8 + q + 4) * APH + m);
        a[3] = *(const uint32_t*)(Asm + (kg * 8 + q + 4) * APH + m + 8);
#pragma unroll
        for (int nj = 0; nj < 4; ++nj) {
            uint2 b = Bu[(kg * 4 + q) * Q_BPR + n0w + nj * 8 + g];
            mma_f16(acc[nj], a, b.x, b.y);
        }
    }
}

__device__ void q_path(int bid, int t, char* smraw,
                       const float* __restrict__ feat,
                       const float* __restrict__ flow,
                       const float* __restrict__ qw,
                       const float* __restrict__ qb) {
    __half2* Asm = (__half2*)smraw;
    uint2*   Bu  = (uint2*)(smraw + 4 * A_STG_H2 * 4);
    __shared__ float s_base[2 * MT * 128];
    __shared__ float s_idt[32];

    int m0_blk = bid * (128 * MT);
    int n      = m0_blk / HWSZ;
    int pix0_blk = m0_blk % HWSZ;

    ARegs ra[2];
    ldgA(ra[0], feat, n, pix0_blk, 0, t);
    ldgA(ra[1], feat, n, pix0_blk, 1, t);

#pragma unroll
    for (int j = 0; j < 4; ++j) {
        int idx = j * 1024 + t;
        int pr = idx >> 7, nn = idx & 127;
        int cc = pr >> 3, kg = (pr >> 2) & 1, qq = pr & 3;
        int kpp = cc * 16 + kg * 8 + qq;
        float w0 = qw[(2 * kpp) * DIM + nn];
        float w1 = qw[(2 * kpp + 1) * DIM + nn];
        float w2 = qw[(2 * kpp + 8) * DIM + nn];
        float w3 = qw[(2 * kpp + 9) * DIM + nn];
        uint2 u;
        u.x = h2bits(__floats2half2_rn(w0, w1));
        u.y = h2bits(__floats2half2_rn(w2, w3));
        Bu[pr * Q_BPR + nn] = u;
    }

    if (t < 32) s_idt[t] = inv_dt(t);
    {
        int idx = t;
        int half = idx >> 9;
        int tile = (idx >> 7) & 3;
        int m    = idx & 127;
        int pix  = pix0_blk + tile * 128 + m;
        int yy = pix / WW, xx = pix % WW;
        const float* fl = flow + (size_t)((n * HH + yy) * WW + xx) * 2;
        float fx = fl[0], fy = fl[1];
        float full = half ? ((float)xx + fx) : ((float)yy + fy);
        float dec  = full - floorf(full);
        s_base[(half * MT + tile) * 128 + m] = dec * (6.283185307179586f / 2.000001f);
    }
    __syncthreads();

    stsA_q(Asm, ra[0], 0, t, s_base, s_idt);
    stsA_q(Asm, ra[1], 1, t, s_base, s_idt);
    ldgA(ra[0], feat, n, pix0_blk, 2, t);
    ldgA(ra[1], feat, n, pix0_blk, 3, t);
    __syncthreads();

    int w = t >> 5, lane = t & 31;
    int m0w = (w & 7) * 16, n0w = (w >> 3) * 32;
    int q = lane & 3, g = lane >> 2;

    float acc[4][4];
#pragma unroll
    for (int nj = 0; nj < 4; ++nj)
#pragma unroll
        for (int e = 0; e < 4; ++e) acc[nj][e] = 0.f;

    const float sc = 0.25f;

#pragma unroll 1
    for (int gp = 0; gp < 8; ++gp) {
        int c0 = 2 * gp, c1 = c0 + 1;
        if (gp <= 6) {
            stsA_q(Asm, ra[0], c0 + 2, t, s_base, s_idt);
            stsA_q(Asm, ra[1], c1 + 2, t, s_base, s_idt);
        }
        if (gp <= 5) {
            ldgA(ra[0], feat, n, pix0_blk, c0 + 4, t);
            ldgA(ra[1], feat, n, pix0_blk, c1 + 4, t);
        }
        mma_chunk_q(Asm + (c0 & 3) * A_STG_H2, Bu + ((c0 & 3) * 8) * Q_BPR,
                    acc, m0w, n0w, q, g);
        mma_chunk_q(Asm + (c1 & 3) * A_STG_H2, Bu + ((c1 & 3) * 8) * Q_BPR,
                    acc, m0w, n0w, q, g);

        if (gp & 1) {
            int m0 = m0_blk + (gp >> 1) * 128;
#pragma unroll
            for (int nj = 0; nj < 4; ++nj) {
                int r0 = m0 + m0w + g;
                int cb = n0w + nj * 8 + q * 2;
                float b0 = qb[cb], b1 = qb[cb + 1];
                *(__half2*)(g_Q + (size_t)r0 * DIM + cb) =
                    __floats2half2_rn((acc[nj][0] + b0) * sc, (acc[nj][1] + b1) * sc);
                *(__half2*)(g_Q + (size_t)(r0 + 8) * DIM + cb) =
                    __floats2half2_rn((acc[nj][2] + b0) * sc, (acc[nj][3] + b1) * sc);
                acc[nj][0] = 0.f; acc[nj][1] = 0.f;
                acc[nj][2] = 0.f; acc[nj][3] = 0.f;
            }
        }
        __syncthreads();
    }
}

// ---------------------------------------------------------------------------
// Merged prep kernel: [bias | kv | q] by block range
// ---------------------------------------------------------------------------
__global__ __launch_bounds__(1024, 1)
void prep_kernel(const float* __restrict__ feat_supp,
                 const float* __restrict__ feat_curr,
                 const float* __restrict__ flow,
                 const float* __restrict__ qw, const float* __restrict__ qb,
                 const float* __restrict__ kw, const float* __restrict__ kb,
                 const float* __restrict__ vw, const float* __restrict__ vb) {
    extern __shared__ char smraw[];
    int t = threadIdx.x;
    int b = blockIdx.x;
    if (b < NBLK_BIAS) {
        bias_path(b, t, kw, kb, vw, vb);
    } else if (b < NBLK_BIAS + NBLK_GEMM) {
        kv_path(b - NBLK_BIAS, t, smraw, feat_supp, kw, vw);
    } else {
        q_path(b - NBLK_BIAS - NBLK_GEMM, t, smraw, feat_curr, flow, qw, qb);
    }
}

// ---------------------------------------------------------------------------
// Attention: 512 thr, 32 px/CTA, 2 px/warp; head = 2 lanes (xor-1).
// Split K-phase / V-phase to cut live registers; target 3 CTAs/SM.
// ---------------------------------------------------------------------------
#define OPIT 129

__global__ __launch_bounds__(512, 3)
void attn_kernel(const float* __restrict__ flow, float* __restrict__ out) {
    __shared__ float s_out[32 * OPIT];
    __shared__ float s_kb[NWP * DIM];
    __shared__ float s_vb[NWP * DIM];
    int t = threadIdx.x;
    if (t < NWP * DIM) {
        s_kb[t] = g_kb[t];
        s_vb[t] = g_vb[t];
    }
    __syncthreads();

    int warp = t >> 5, lane = t & 31;
    int sub = lane >> 4, sl = lane & 15;
    int pidx = warp * 2 + sub;
    int p   = blockIdx.x * 32 + pidx;
    int n   = p / HWSZ;
    int pix = p % HWSZ;
    int y = pix / WW, x = pix % WW;

    const float* fl = flow + (size_t)((n * HH + y) * WW + x) * 2;
    float fx = fl[0], fy = fl[1];
    int giy = (int)floorf((float)y + fy);
    int gix = (int)floorf((float)x + fx);

    int nb[4];
#pragma unroll
    for (int w2 = 0; w2 < 4; ++w2) {
        int hy = giy + (w2 >> 1);
        int wx = gix + (w2 & 1);
        hy = hy < 0 ? 0 : (hy > HH - 1 ? HH - 1 : hy);
        wx = wx < 0 ? 0 : (wx > WW - 1 ? WW - 1 : wx);
        nb[w2] = n * HWSZ + hy * WW + wx;
    }

    int c0 = sl * 8;
    uint4 qraw = *(const uint4*)(g_Q + (size_t)p * DIM + c0);

    // --- K phase: batch 4 K-row loads, compute per-head logits ---
    uint4 kraw[4];
#pragma unroll
    for (int w2 = 0; w2 < 4; ++w2)
        kraw[w2] = *(const uint4*)(g_K + (size_t)nb[w2] * DIM + c0);

    float2 q01 = __half22float2(*(__half2*)&qraw.x);
    float2 q23 = __half22float2(*(__half2*)&qraw.y);
    float2 q45 = __half22float2(*(__half2*)&qraw.z);
    float2 q67 = __half22float2(*(__half2*)&qraw.w);

    float lg[4];
#pragma unroll
    for (int w2 = 0; w2 < 4; ++w2) {
        float2 k01 = __half22float2(*(__half2*)&kraw[w2].x);
        float2 k23 = __half22float2(*(__half2*)&kraw[w2].y);
        float2 k45 = __half22float2(*(__half2*)&kraw[w2].z);
        float2 k67 = __half22float2(*(__half2*)&kraw[w2].w);
        const float* kbp = s_kb + w2 * DIM + c0;
        float part = q01.x * (k01.x + kbp[0]) + q01.y * (k01.y + kbp[1]) +
                     q23.x * (k23.x + kbp[2]) + q23.y * (k23.y + kbp[3]) +
                     q45.x * (k45.x + kbp[4]) + q45.y * (k45.y + kbp[5]) +
                     q67.x * (k67.x + kbp[6]) + q67.y * (k67.y + kbp[7]);
        part += __shfl_xor_sync(0xffffffffu, part, 1);   // head = 2 lanes
        lg[w2] = part;
    }

    // --- V phase: batch 4 V-row loads, softmax-weighted accumulate ---
    uint4 vraw[4];
#pragma unroll
    for (int w2 = 0; w2 < 4; ++w2)
        vraw[w2] = *(const uint4*)(g_V + (size_t)nb[w2] * DIM + c0);

    float mx = fmaxf(fmaxf(lg[0], lg[1]), fmaxf(lg[2], lg[3]));
    float e0 = __expf(lg[0] - mx), e1 = __expf(lg[1] - mx);
    float e2 = __expf(lg[2] - mx), e3 = __expf(lg[3] - mx);
    float inv = 1.f / (e0 + e1 + e2 + e3);
    float aw[4] = {e0 * inv, e1 * inv, e2 * inv, e3 * inv};

    float o[8] = {0.f, 0.f, 0.f, 0.f, 0.f, 0.f, 0.f, 0.f};
#pragma unroll
    for (int w2 = 0; w2 < 4; ++w2) {
        float2 v01 = __half22float2(*(__half2*)&vraw[w2].x);
        float2 v23 = __half22float2(*(__half2*)&vraw[w2].y);
        float2 v45 = __half22float2(*(__half2*)&vraw[w2].z);
        float2 v67 = __half22float2(*(__half2*)&vraw[w2].w);
        const float* vbp = s_vb + w2 * DIM + c0;
        float a = aw[w2];
        o[0] += a * (v01.x + vbp[0]);
        o[1] += a * (v01.y + vbp[1]);
        o[2] += a * (v23.x + vbp[2]);
        o[3] += a * (v23.y + vbp[3]);
        o[4] += a * (v45.x + vbp[4]);
        o[5] += a * (v45.y + vbp[5]);
        o[6] += a * (v67.x + vbp[6]);
        o[7] += a * (v67.y + vbp[7]);
    }
#pragma unroll
    for (int i = 0; i < 8; ++i)
        s_out[pidx * OPIT + c0 + i] = o[i];
    __syncthreads();

    int p0   = blockIdx.x * 32;
    int n0   = p0 / HWSZ;
    int pix0 = p0 % HWSZ;
    int y0 = pix0 / WW, x0 = pix0 % WW;
#pragma unroll
    for (int j = 0; j < 8; ++j) {
        int d = warp + j * 16;
        out[((size_t)(n0 * DIM + d) * HH + y0) * WW + x0 + lane] =
            s_out[lane * OPIT + d];
    }
}

// ---------------------------------------------------------------------------
extern "C" void kernel_launch(void* const* d_in, const int* in_sizes, int n_in,
                              void* d_out, int out_size) {
    const float* feat_supp = (const float*)d_in[0];
    const float* feat_curr = (const float*)d_in[1];
    const float* flow      = (const float*)d_in[2];
    const float* q_w       = (const float*)d_in[3];
    const float* q_b       = (const float*)d_in[4];
    const float* k_w       = (const float*)d_in[5];
    const float* k_b       = (const float*)d_in[6];
    const float* v_w       = (const float*)d_in[7];
    const float* v_b       = (const float*)d_in[8];
    float* out = (float*)d_out;

    const int smem_prep = 4 * A_STG_H2 * 4 + 32 * KV_BPR * 8;  // 101376 B
    cudaFuncSetAttribute(prep_kernel, cudaFuncAttributeMaxDynamicSharedMemorySize, smem_prep);

    prep_kernel<<<NBLK_BIAS + 2 * NBLK_GEMM, 1024, smem_prep>>>(
        feat_supp, feat_curr, flow, q_w, q_b, k_w, k_b, v_w, v_b);
    attn_kernel<<<NHW / 32, 512>>>(flow, out);
}

// round 16
// speedup vs baseline: 1.2845x; 1.0285x over previous
#include <cuda_runtime.h>
#include <cuda_fp16.h>
#include <math.h>
#include <stdint.h>

// Problem constants
#define NB   4
#define CC   128
#define HH   128
#define WW   256
#define HWSZ (HH * WW)          // 32768
#define NHW  (NB * HWSZ)        // 131072
#define DIM  128
#define NWP  4
#define MTILE 64                // pixels per m-tile
#define MT   8                  // m-tiles per CTA (512 pixels)
#define NCH  (MT * 4)           // 32 chunks per CTA
#define APH  72                 // A pitch (half2 units); 72%32==8 -> conflict-free
#define A_STG_H2 (16 * APH)     // half2 per A stage = 1152
#define KV_BPR 260              // kv B pitch (uint2); words 520 %32==8
#define Q_BPR  132              // q  B pitch (uint2); words 264 %32==8
#define NBLK_GEMM (NHW / (MTILE * MT)) // 256
#define NBLK_BIAS 8

// Device-global scratch: K/V/Q fp16 (fp32 accumulate everywhere)
__device__ __half g_K[(size_t)NHW * DIM];
__device__ __half g_V[(size_t)NHW * DIM];
__device__ __half g_Q[(size_t)NHW * DIM];
__device__ float  g_kb[NWP * DIM];
__device__ float  g_vb[NWP * DIM];

__device__ __forceinline__ float inv_dt(int t2) {
    return exp2f(-(float)t2 * (13.287712379549449f / 32.0f));
}
__device__ __forceinline__ uint32_t h2bits(__half2 h) {
    return *reinterpret_cast<uint32_t*>(&h);
}

__device__ __forceinline__ void mma_f16(float d[4], const uint32_t a[4],
                                        uint32_t b0, uint32_t b1) {
    asm volatile(
        "mma.sync.aligned.m16n8k16.row.col.f32.f16.f16.f32 "
        "{%0,%1,%2,%3}, {%4,%5,%6,%7}, {%8,%9}, {%0,%1,%2,%3};\n"
        : "+f"(d[0]), "+f"(d[1]), "+f"(d[2]), "+f"(d[3])
        : "r"(a[0]), "r"(a[1]), "r"(a[2]), "r"(a[3]), "r"(b0), "r"(b1));
}

// ---------------------------------------------------------------------------
// Bias path (blocks 0..7); 512 threads
// ---------------------------------------------------------------------------
__device__ void bias_path(int bid, int t,
                          const float* __restrict__ kw, const float* __restrict__ kb,
                          const float* __restrict__ vw, const float* __restrict__ vb) {
    __shared__ float pb[DIM];
    int w      = bid & 3;
    int matrix = bid >> 2;
    if (t < DIM) {
        int oy = w >> 1, ox = w & 1;
        float coord = (t < 64) ? (float)oy : (float)ox;
        int ii = t & 63;
        int t2 = ii >> 1;
        float arg = coord * (6.283185307179586f / 1.000001f) * inv_dt(t2);
        float s, c;
        sincosf(arg, &s, &c);
        pb[t] = (ii & 1) ? c : s;
    }
    __syncthreads();

    const float* W  = matrix ? vw : kw;
    const float* Bb = matrix ? vb : kb;
    float* dst      = matrix ? g_vb : g_kb;

    int d = t >> 2, q = t & 3;
    float acc = 0.f;
    int cbase = q * 32;
#pragma unroll 8
    for (int c = 0; c < 32; ++c)
        acc += pb[cbase + c] * W[(cbase + c) * DIM + d];
    acc += __shfl_xor_sync(0xffffffffu, acc, 1);
    acc += __shfl_xor_sync(0xffffffffu, acc, 2);
    if (q == 0)
        dst[w * DIM + d] = acc + Bb[d];
}

// ---------------------------------------------------------------------------
// A fill (512 thr): LDG fp32 -> cvt -> STS fp16. 4 stages, m-tile 64.
// thread t: kp = t>>5 (0..15), m2 = t&31 (pixel pair within tile)
// ---------------------------------------------------------------------------
struct ARegs { float2 r0, r1; };

__device__ __forceinline__ void ldgA(ARegs& ra, const float* __restrict__ feat,
                                     int n, int pix0_blk, int gc, int t) {
    int kp = t >> 5, m2 = t & 31;
    int kb = (gc & 3) * 32, tile = gc >> 2;
    int pix = pix0_blk + tile * MTILE + m2 * 2;
    const float* p = feat + (size_t)(n * CC + kb + 2 * kp) * HWSZ + pix;
    ra.r0 = *(const float2*)p;
    ra.r1 = *(const float2*)(p + HWSZ);
}

__device__ __forceinline__ void stsA_kv(__half2* __restrict__ Asm,
                                        const ARegs& ra, int gc, int t) {
    int kp = t >> 5, m2 = t & 31;
    __half2* dst = Asm + (gc & 3) * A_STG_H2 + kp * APH + m2 * 2;
    uint2 u;
    u.x = h2bits(__floats2half2_rn(ra.r0.x, ra.r1.x));
    u.y = h2bits(__floats2half2_rn(ra.r0.y, ra.r1.y));
    *(uint2*)dst = u;
}

__device__ __forceinline__ void stsA_q(__half2* __restrict__ Asm, const ARegs& ra,
                                       int gc, int t,
                                       const float* __restrict__ s_base,
                                       const float* __restrict__ s_idt) {
    int kp = t >> 5, m2 = t & 31;
    int kb = (gc & 3) * 32, tile = gc >> 2;
    int c0 = kb + 2 * kp;
    int half = (c0 >> 6) & 1;
    int t2 = (c0 & 63) >> 1;
    float f = s_idt[t2];
    const float* bp = s_base + (half * MT + tile) * MTILE + m2 * 2;
    float sa, ca, sb, cb;
    __sincosf(bp[0] * f, &sa, &ca);
    __sincosf(bp[1] * f, &sb, &cb);
    __half2* dst = Asm + (gc & 3) * A_STG_H2 + kp * APH + m2 * 2;
    uint2 u;
    u.x = h2bits(__floats2half2_rn(ra.r0.x + sa, ra.r1.x + ca));
    u.y = h2bits(__floats2half2_rn(ra.r0.y + sb, ra.r1.y + cb));
    *(uint2*)dst = u;
}

// ---------------------------------------------------------------------------
// KV path: 16 warps (2m x 8n), m32 x n32 warp tile over 64x256 tile.
// ---------------------------------------------------------------------------
__device__ __forceinline__ void mma_chunk_kv(const __half2* __restrict__ Asm,
                                             const uint2* __restrict__ Bu,
                                             float acc[2][4][4],
                                             int m0w, int n0w, int q, int g) {
#pragma unroll
    for (int kg = 0; kg < 2; ++kg) {
        uint32_t a[2][4];
#pragma unroll
        for (int mi = 0; mi < 2; ++mi) {
            int m = m0w + mi * 16 + g;
            a[mi][0] = *(const uint32_t*)(Asm + (kg * 8 + q) * APH + m);
            a[mi][1] = *(const uint32_t*)(Asm + (kg * 8 + q) * APH + m + 8);
            a[mi][2] = *(const uint32_t*)(Asm + (kg * 8 + q + 4) * APH + m);
            a[mi][3] = *(const uint32_t*)(Asm + (kg * 8 + q + 4) * APH + m + 8);
        }
#pragma unroll
        for (int nj = 0; nj < 4; ++nj) {
            uint2 b = Bu[(kg * 4 + q) * KV_BPR + n0w + nj * 8 + g];
#pragma unroll
            for (int mi = 0; mi < 2; ++mi)
                mma_f16(acc[mi][nj], a[mi], b.x, b.y);
        }
    }
}

__device__ void kv_path(int bid, int t, char* smraw,
                        const float* __restrict__ feat,
                        const float* __restrict__ kw,
                        const float* __restrict__ vw) {
    __half2* Asm = (__half2*)smraw;
    uint2*   Bu  = (uint2*)(smraw + 4 * A_STG_H2 * 4);

    int m0_blk = bid * (MTILE * MT);
    int n      = m0_blk / HWSZ;
    int pix0_blk = m0_blk % HWSZ;

    ARegs ra[2];
    ldgA(ra[0], feat, n, pix0_blk, 0, t);
    ldgA(ra[1], feat, n, pix0_blk, 1, t);

    // B panel: 32 pr-rows x 256 cols, fp16 k-pair-interleaved
#pragma unroll
    for (int j = 0; j < 16; ++j) {
        int idx = j * 512 + t;
        int pr = idx >> 8, nn = idx & 255;
        int cc = pr >> 3, kg = (pr >> 2) & 1, qq = pr & 3;
        int kpp = cc * 16 + kg * 8 + qq;
        const float* W = (nn < 128) ? kw : vw;
        int col = nn & 127;
        float w0 = W[(2 * kpp) * DIM + col];
        float w1 = W[(2 * kpp + 1) * DIM + col];
        float w2 = W[(2 * kpp + 8) * DIM + col];
        float w3 = W[(2 * kpp + 9) * DIM + col];
        uint2 u;
        u.x = h2bits(__floats2half2_rn(w0, w1));
        u.y = h2bits(__floats2half2_rn(w2, w3));
        Bu[pr * KV_BPR + nn] = u;
    }

    stsA_kv(Asm, ra[0], 0, t);
    stsA_kv(Asm, ra[1], 1, t);
    ldgA(ra[0], feat, n, pix0_blk, 2, t);
    ldgA(ra[1], feat, n, pix0_blk, 3, t);
    __syncthreads();

    int w = t >> 5, lane = t & 31;
    int m0w = (w & 1) * 32, n0w = (w >> 1) * 32;
    int q = lane & 3, g = lane >> 2;

    float acc[2][4][4];
#pragma unroll
    for (int mi = 0; mi < 2; ++mi)
#pragma unroll
        for (int nj = 0; nj < 4; ++nj)
#pragma unroll
            for (int e = 0; e < 4; ++e) acc[mi][nj][e] = 0.f;

#pragma unroll 1
    for (int gp = 0; gp < NCH / 2; ++gp) {
        int c0 = 2 * gp, c1 = c0 + 1;
        if (gp <= NCH / 2 - 2) { stsA_kv(Asm, ra[0], c0 + 2, t); stsA_kv(Asm, ra[1], c1 + 2, t); }
        if (gp <= NCH / 2 - 3) {
            ldgA(ra[0], feat, n, pix0_blk, c0 + 4, t);
            ldgA(ra[1], feat, n, pix0_blk, c1 + 4, t);
        }
        mma_chunk_kv(Asm + (c0 & 3) * A_STG_H2, Bu + ((c0 & 3) * 8) * KV_BPR,
                     acc, m0w, n0w, q, g);
        mma_chunk_kv(Asm + (c1 & 3) * A_STG_H2, Bu + ((c1 & 3) * 8) * KV_BPR,
                     acc, m0w, n0w, q, g);

        if (gp & 1) {
            int m0 = m0_blk + (gp >> 1) * MTILE;
#pragma unroll
            for (int mi = 0; mi < 2; ++mi) {
#pragma unroll
                for (int nj = 0; nj < 4; ++nj) {
                    int r0 = m0 + m0w + mi * 16 + g;
                    int col = n0w + nj * 8 + q * 2;
                    __half* dst = (col < 128) ? (g_K + (size_t)r0 * DIM + col)
                                              : (g_V + (size_t)r0 * DIM + (col - 128));
                    *(__half2*)dst = __floats2half2_rn(acc[mi][nj][0], acc[mi][nj][1]);
                    *(__half2*)(dst + (size_t)8 * DIM) =
                        __floats2half2_rn(acc[mi][nj][2], acc[mi][nj][3]);
                    acc[mi][nj][0] = 0.f; acc[mi][nj][1] = 0.f;
                    acc[mi][nj][2] = 0.f; acc[mi][nj][3] = 0.f;
                }
            }
        }
        __syncthreads();
    }
}

// ---------------------------------------------------------------------------
// Q path: 16 warps (4m x 4n), m16 x n32 tile over 64x128; PE fused in fill
// ---------------------------------------------------------------------------
__device__ __forceinline__ void mma_chunk_q(const __half2* __restrict__ Asm,
                                            const uint2* __restrict__ Bu,
                                            float acc[4][4],
                                            int m0w, int n0w, int q, int g) {
#pragma unroll
    for (int kg = 0; kg < 2; ++kg) {
        uint32_t a[4];
        int m = m0w + g;
        a[0] = *(const uint32_t*)(Asm + (kg * 8 + q) * APH + m);
        a[1] = *(const uint32_t*)(Asm + (kg * 8 + q) * APH + m + 8);
        a[2] = *(const uint32_t*)(Asm + (kg * 8 + q + 4) * APH + m);
        a[3] = *(const uint32_t*)(Asm + (kg * 8 + q + 4) * APH + m + 8);
#pragma unroll
        for (int nj = 0; nj < 4; ++nj) {
            uint2 b = Bu[(kg * 4 + q) * Q_BPR + n0w + nj * 8 + g];
            mma_f16(acc[nj], a, b.x, b.y);
        }
    }
}

__device__ void q_path(int bid, int t, char* smraw,
                       const float* __restrict__ feat,
                       const float* __restrict__ flow,
                       const float* __restrict__ qw,
                       const float* __restrict__ qb) {
    __half2* Asm = (__half2*)smraw;
    uint2*   Bu  = (uint2*)(smraw + 4 * A_STG_H2 * 4);
    __shared__ float s_base[2 * MT * MTILE];   // 1024 floats
    __shared__ float s_idt[32];

    int m0_blk = bid * (MTILE * MT);
    int n      = m0_blk / HWSZ;
    int pix0_blk = m0_blk % HWSZ;

    ARegs ra[2];
    ldgA(ra[0], feat, n, pix0_blk, 0, t);
    ldgA(ra[1], feat, n, pix0_blk, 1, t);

    // B panel (q_w): 32 pr-rows x 128 cols
#pragma unroll
    for (int j = 0; j < 8; ++j) {
        int idx = j * 512 + t;
        int pr = idx >> 7, nn = idx & 127;
        int cc = pr >> 3, kg = (pr >> 2) & 1, qq = pr & 3;
        int kpp = cc * 16 + kg * 8 + qq;
        float w0 = qw[(2 * kpp) * DIM + nn];
        float w1 = qw[(2 * kpp + 1) * DIM + nn];
        float w2 = qw[(2 * kpp + 8) * DIM + nn];
        float w3 = qw[(2 * kpp + 9) * DIM + nn];
        uint2 u;
        u.x = h2bits(__floats2half2_rn(w0, w1));
        u.y = h2bits(__floats2half2_rn(w2, w3));
        Bu[pr * Q_BPR + nn] = u;
    }

    if (t < 32) s_idt[t] = inv_dt(t);
#pragma unroll
    for (int j = 0; j < 2; ++j) {
        int idx = j * 512 + t;                 // 0..1023
        int half = idx >> 9;
        int tile = (idx >> 6) & 7;
        int m    = idx & 63;
        int pix  = pix0_blk + tile * MTILE + m;
        int yy = pix / WW, xx = pix % WW;
        const float* fl = flow + (size_t)((n * HH + yy) * WW + xx) * 2;
        float fx = fl[0], fy = fl[1];
        float full = half ? ((float)xx + fx) : ((float)yy + fy);
        float dec  = full - floorf(full);
        s_base[(half * MT + tile) * MTILE + m] = dec * (6.283185307179586f / 2.000001f);
    }
    __syncthreads();

    stsA_q(Asm, ra[0], 0, t, s_base, s_idt);
    stsA_q(Asm, ra[1], 1, t, s_base, s_idt);
    ldgA(ra[0], feat, n, pix0_blk, 2, t);
    ldgA(ra[1], feat, n, pix0_blk, 3, t);
    __syncthreads();

    int w = t >> 5, lane = t & 31;
    int m0w = (w & 3) * 16, n0w = (w >> 2) * 32;
    int q = lane & 3, g = lane >> 2;

    float acc[4][4];
#pragma unroll
    for (int nj = 0; nj < 4; ++nj)
#pragma unroll
        for (int e = 0; e < 4; ++e) acc[nj][e] = 0.f;

    const float sc = 0.25f;

#pragma unroll 1
    for (int gp = 0; gp < NCH / 2; ++gp) {
        int c0 = 2 * gp, c1 = c0 + 1;
        if (gp <= NCH / 2 - 2) {
            stsA_q(Asm, ra[0], c0 + 2, t, s_base, s_idt);
            stsA_q(Asm, ra[1], c1 + 2, t, s_base, s_idt);
        }
        if (gp <= NCH / 2 - 3) {
            ldgA(ra[0], feat, n, pix0_blk, c0 + 4, t);
            ldgA(ra[1], feat, n, pix0_blk, c1 + 4, t);
        }
        mma_chunk_q(Asm + (c0 & 3) * A_STG_H2, Bu + ((c0 & 3) * 8) * Q_BPR,
                    acc, m0w, n0w, q, g);
        mma_chunk_q(Asm + (c1 & 3) * A_STG_H2, Bu + ((c1 & 3) * 8) * Q_BPR,
                    acc, m0w, n0w, q, g);

        if (gp & 1) {
            int m0 = m0_blk + (gp >> 1) * MTILE;
#pragma unroll
            for (int nj = 0; nj < 4; ++nj) {
                int r0 = m0 + m0w + g;
                int cb = n0w + nj * 8 + q * 2;
                float b0 = qb[cb], b1 = qb[cb + 1];
                *(__half2*)(g_Q + (size_t)r0 * DIM + cb) =
                    __floats2half2_rn((acc[nj][0] + b0) * sc, (acc[nj][1] + b1) * sc);
                *(__half2*)(g_Q + (size_t)(r0 + 8) * DIM + cb) =
                    __floats2half2_rn((acc[nj][2] + b0) * sc, (acc[nj][3] + b1) * sc);
                acc[nj][0] = 0.f; acc[nj][1] = 0.f;
                acc[nj][2] = 0.f; acc[nj][3] = 0.f;
            }
        }
        __syncthreads();
    }
}

// ---------------------------------------------------------------------------
// Merged prep kernel: [bias | kv | q], 512 threads, 2 CTAs/SM
// ---------------------------------------------------------------------------
__global__ __launch_bounds__(512, 2)
void prep_kernel(const float* __restrict__ feat_supp,
                 const float* __restrict__ feat_curr,
                 const float* __restrict__ flow,
                 const float* __restrict__ qw, const float* __restrict__ qb,
                 const float* __restrict__ kw, const float* __restrict__ kb,
                 const float* __restrict__ vw, const float* __restrict__ vb) {
    extern __shared__ char smraw[];
    int t = threadIdx.x;
    int b = blockIdx.x;
    if (b < NBLK_BIAS) {
        bias_path(b, t, kw, kb, vw, vb);
    } else if (b < NBLK_BIAS + NBLK_GEMM) {
        kv_path(b - NBLK_BIAS, t, smraw, feat_supp, kw, vw);
    } else {
        q_path(b - NBLK_BIAS - NBLK_GEMM, t, smraw, feat_curr, flow, qw, qb);
    }
}

// ---------------------------------------------------------------------------
// Attention (R14 best): 512 thr, 32 px/CTA, 2 px/warp; head = 2 lanes (xor-1)
// ---------------------------------------------------------------------------
#define OPIT 129

__global__ __launch_bounds__(512, 2)
void attn_kernel(const float* __restrict__ flow, float* __restrict__ out) {
    __shared__ float s_out[32 * OPIT];
    __shared__ float s_kb[NWP * DIM];
    __shared__ float s_vb[NWP * DIM];
    int t = threadIdx.x;
    if (t < NWP * DIM) {
        s_kb[t] = g_kb[t];
        s_vb[t] = g_vb[t];
    }
    __syncthreads();

    int warp = t >> 5, lane = t & 31;
    int sub = lane >> 4, sl = lane & 15;
    int pidx = warp * 2 + sub;
    int p   = blockIdx.x * 32 + pidx;
    int n   = p / HWSZ;
    int pix = p % HWSZ;
    int y = pix / WW, x = pix % WW;

    const float* fl = flow + (size_t)((n * HH + y) * WW + x) * 2;
    float fx = fl[0], fy = fl[1];
    int giy = (int)floorf((float)y + fy);
    int gix = (int)floorf((float)x + fx);

    int c0 = sl * 8;
    uint4 qraw = *(const uint4*)(g_Q + (size_t)p * DIM + c0);
    float2 q01 = __half22float2(*(__half2*)&qraw.x);
    float2 q23 = __half22float2(*(__half2*)&qraw.y);
    float2 q45 = __half22float2(*(__half2*)&qraw.z);
    float2 q67 = __half22float2(*(__half2*)&qraw.w);

    int nb[4];
#pragma unroll
    for (int w2 = 0; w2 < 4; ++w2) {
        int hy = giy + (w2 >> 1);
        int wx = gix + (w2 & 1);
        hy = hy < 0 ? 0 : (hy > HH - 1 ? HH - 1 : hy);
        wx = wx < 0 ? 0 : (wx > WW - 1 ? WW - 1 : wx);
        nb[w2] = n * HWSZ + hy * WW + wx;
    }
    uint4 kraw[4], vraw[4];
#pragma unroll
    for (int w2 = 0; w2 < 4; ++w2) {
        kraw[w2] = *(const uint4*)(g_K + (size_t)nb[w2] * DIM + c0);
        vraw[w2] = *(const uint4*)(g_V + (size_t)nb[w2] * DIM + c0);
    }

    float lg[4];
#pragma unroll
    for (int w2 = 0; w2 < 4; ++w2) {
        float2 k01 = __half22float2(*(__half2*)&kraw[w2].x);
        float2 k23 = __half22float2(*(__half2*)&kraw[w2].y);
        float2 k45 = __half22float2(*(__half2*)&kraw[w2].z);
        float2 k67 = __half22float2(*(__half2*)&kraw[w2].w);
        const float* kbp = s_kb + w2 * DIM + c0;
        float part = q01.x * (k01.x + kbp[0]) + q01.y * (k01.y + kbp[1]) +
                     q23.x * (k23.x + kbp[2]) + q23.y * (k23.y + kbp[3]) +
                     q45.x * (k45.x + kbp[4]) + q45.y * (k45.y + kbp[5]) +
                     q67.x * (k67.x + kbp[6]) + q67.y * (k67.y + kbp[7]);
        part += __shfl_xor_sync(0xffffffffu, part, 1);   // head = 2 lanes
        lg[w2] = part;
    }
    float mx = fmaxf(fmaxf(lg[0], lg[1]), fmaxf(lg[2], lg[3]));
    float e0 = __expf(lg[0] - mx), e1 = __expf(lg[1] - mx);
    float e2 = __expf(lg[2] - mx), e3 = __expf(lg[3] - mx);
    float inv = 1.f / (e0 + e1 + e2 + e3);
    float aw[4] = {e0 * inv, e1 * inv, e2 * inv, e3 * inv};

    float o[8] = {0.f, 0.f, 0.f, 0.f, 0.f, 0.f, 0.f, 0.f};
#pragma unroll
    for (int w2 = 0; w2 < 4; ++w2) {
        float2 v01 = __half22float2(*(__half2*)&vraw[w2].x);
        float2 v23 = __half22float2(*(__half2*)&vraw[w2].y);
        float2 v45 = __half22float2(*(__half2*)&vraw[w2].z);
        float2 v67 = __half22float2(*(__half2*)&vraw[w2].w);
        const float* vbp = s_vb + w2 * DIM + c0;
        float a = aw[w2];
        o[0] += a * (v01.x + vbp[0]);
        o[1] += a * (v01.y + vbp[1]);
        o[2] += a * (v23.x + vbp[2]);
        o[3] += a * (v23.y + vbp[3]);
        o[4] += a * (v45.x + vbp[4]);
        o[5] += a * (v45.y + vbp[5]);
        o[6] += a * (v67.x + vbp[6]);
        o[7] += a * (v67.y + vbp[7]);
    }
#pragma unroll
    for (int i = 0; i < 8; ++i)
        s_out[pidx * OPIT + c0 + i] = o[i];
    __syncthreads();

    int p0   = blockIdx.x * 32;
    int n0   = p0 / HWSZ;
    int pix0 = p0 % HWSZ;
    int y0 = pix0 / WW, x0 = pix0 % WW;
#pragma unroll
    for (int j = 0; j < 8; ++j) {
        int d = warp + j * 16;
        out[((size_t)(n0 * DIM + d) * HH + y0) * WW + x0 + lane] =
            s_out[lane * OPIT + d];
    }
}

// ---------------------------------------------------------------------------
extern "C" void kernel_launch(void* const* d_in, const int* in_sizes, int n_in,
                              void* d_out, int out_size) {
    const float* feat_supp = (const float*)d_in[0];
    const float* feat_curr = (const float*)d_in[1];
    const float* flow      = (const float*)d_in[2];
    const float* q_w       = (const float*)d_in[3];
    const float* q_b       = (const float*)d_in[4];
    const float* k_w       = (const float*)d_in[5];
    const float* k_b       = (const float*)d_in[6];
    const float* v_w       = (const float*)d_in[7];
    const float* v_b       = (const float*)d_in[8];
    float* out = (float*)d_out;

    const int smem_prep = 4 * A_STG_H2 * 4 + 32 * KV_BPR * 8;  // 18432+66560 = 84992 B
    cudaFuncSetAttribute(prep_kernel, cudaFuncAttributeMaxDynamicSharedMemorySize, smem_prep);

    prep_kernel<<<NBLK_BIAS + 2 * NBLK_GEMM, 512, smem_prep>>>(
        feat_supp, feat_curr, flow, q_w, q_b, k_w, k_b, v_w, v_b);
    attn_kernel<<<NHW / 32, 512>>>(flow, out);
}